// round 12
// baseline (speedup 1.0000x reference)
#include <cuda_runtime.h>
#include <cuda_fp16.h>
#include <cstdint>

#define NPTS   100000
#define BATCH  16
#define MNB    9
#define NSLOTS (NPTS * 3)              /* per-batch floats, divisible by 4 */
#define TP     128                     /* points per k_diff tile           */
#define QB     (TP * 3 / 4)            /* 96 float4 slots per batch        */
#define ROWB   128                     /* padded row bytes (data in 96B)   */
#define INV_COUNT (1.0f / (float)(BATCH * NPTS * 3))

/* k_lap geometry: 4 warps/block, 5 pts per warp-iter, 8 iters, 3 stages */
#define LAP_WARPS   4
#define LAP_ITERS   8
#define PTS_PER_IT  5
#define NSTAGE      3
#define PTS_PER_WARP (LAP_ITERS * PTS_PER_IT)          /* 40  */
#define PTS_PER_BLK  (LAP_WARPS * PTS_PER_WARP)        /* 160 */
#define LAP_BLOCKS   (NPTS / PTS_PER_BLK)              /* 625, exact */
#define STAGE_B      (8 * 512)         /* 8 neighbors x 512B = 4096B */

// Scratch: d = gt - pr in fp16, padded rows of 128B; row NPTS is all-zero
// (reference's zero-padded pc_ext row). halves [0,48) of row n hold value
// (c,b) at half index c*16+b.
__device__ __half g_dt[(NPTS + 1) * 64];

// ---------------------------------------------------------------------------
// Kernel 1: diff + transpose (B,N,3) -> padded fp16 rows. __ldcs streaming
// reads so the 38MB input stream doesn't evict the scratch from L2.
// ---------------------------------------------------------------------------
__global__ void k_diff(const float* __restrict__ gt, const float* __restrict__ pr,
                       float* __restrict__ out) {
    if (blockIdx.x == 0) {
        if (threadIdx.x == 0) out[0] = 0.0f;
        if (threadIdx.x < 8)   // zero row NPTS (128B)
            ((uint4*)(g_dt + (size_t)NPTS * 64))[threadIdx.x] =
                make_uint4(0u, 0u, 0u, 0u);
    }

    __shared__ float4 s4[QB * 16];     // 24KB
    const float* sf = (const float*)s4;

    int n0 = blockIdx.x * TP;
    int slot0 = n0 * 3;

    for (int i = threadIdx.x; i < 16 * QB; i += 256) {
        int b = i / QB;
        int q = i - b * QB;
        int slot = slot0 + q * 4;
        float4 v = make_float4(0.f, 0.f, 0.f, 0.f);
        if (slot < NSLOTS) {
            float4 g = __ldcs((const float4*)(gt + (size_t)b * NSLOTS + slot));
            float4 p = __ldcs((const float4*)(pr + (size_t)b * NSLOTS + slot));
            v = make_float4(g.x - p.x, g.y - p.y, g.z - p.z, g.w - p.w);
        }
        s4[q * 16 + (b ^ (q & 15))] = v;
    }
    __syncthreads();

    int valid = NPTS - n0;
    if (valid > TP) valid = TP;
    int total2 = valid * 24;
    __half2* outp = (__half2*)g_dt;
    for (int j = threadIdx.x; j < total2; j += 256) {
        int m   = 2 * j;
        int r   = m >> 4;
        int b0  = m & 15;
        int q   = r >> 2;
        int cmp = r & 3;
        float f0 = sf[4 * (q * 16 + (b0       ^ (q & 15))) + cmp];
        float f1 = sf[4 * (q * 16 + ((b0 + 1) ^ (q & 15))) + cmp];
        int p = r / 3, c = r - 3 * p;
        int hidx = (n0 + p) * 64 + c * 16 + b0;
        outp[hidx >> 1] = __floats2half2_rn(f0, f1);
    }
}

// ---------------------------------------------------------------------------
// cp.async helpers
// ---------------------------------------------------------------------------
__device__ __forceinline__ void cpa16(uint32_t saddr, const void* gaddr) {
    asm volatile("cp.async.cg.shared.global [%0], [%1], 16;"
                 :: "r"(saddr), "l"(gaddr));
}
__device__ __forceinline__ void cpa_commit() {       // empty groups are legal
    asm volatile("cp.async.commit_group;");
}
template <int N>
__device__ __forceinline__ void cpa_wait() {
    asm volatile("cp.async.wait_group %0;" :: "n"(N));
}

// ---------------------------------------------------------------------------
// Kernel 2: gather laplacian.
//  - center row == own row n (nb[:,0] is arange): coalesced streaming LDG.128,
//    removed from the random-gather set (8 random gathers/point remain).
//  - 3-stage cp.async pipeline, prefetch-ahead 2, wait_group<2>:
//    16 random 16B loads per warp continuously in flight.
//  - 5 points per warp-iter, 6 lanes/point, lane owns one 16B chunk;
//    each lane reads back only chunks it wrote (no syncwarp).
// ---------------------------------------------------------------------------
__global__ void __launch_bounds__(LAP_WARPS * 32)
k_lap(const int* __restrict__ nb, const float* __restrict__ num,
      float* __restrict__ out) {
    const unsigned FULL = 0xFFFFFFFFu;
    __shared__ __align__(16) char s_buf[LAP_WARPS][NSTAGE][STAGE_B];  // 48KB
    __shared__ int   s_ids[PTS_PER_BLK * MNB];                        // 5.76KB
    __shared__ float s_num[PTS_PER_BLK];
    __shared__ float ws[LAP_WARPS];

    int tid  = threadIdx.x;
    int lane = tid & 31;
    int w    = tid >> 5;
    int P0   = blockIdx.x * PTS_PER_BLK;

    // stage ids + num (coalesced; P0*9 is a multiple of 4)
    {
        const int4* nb4 = (const int4*)(nb + (size_t)P0 * MNB);
        int4* sd4 = (int4*)s_ids;
        #pragma unroll
        for (int i = tid; i < PTS_PER_BLK * MNB / 4; i += LAP_WARPS * 32)
            sd4[i] = nb4[i];
        for (int i = tid; i < PTS_PER_BLK; i += LAP_WARPS * 32)
            s_num[i] = num[P0 + i];
    }
    __syncthreads();

    int g    = lane / 6;                       // point group 0..4 (5: slack)
    int s    = lane - g * 6;                   // chunk 0..5
    bool act = lane < 30;
    const char* base = (const char*)g_dt;
    int coff = s * 16;

    uint32_t sbase;
    {
        void* p = &s_buf[w][0][0];
        asm("{ .reg .u64 t; cvta.to.shared.u64 t, %1; cvt.u32.u64 %0, t; }"
            : "=r"(sbase) : "l"(p));
    }
    uint32_t soff = lane * 16;                 // lanes 30,31 -> slack bytes

    // issue the 8 random neighbor gathers for iteration it into its stage
    auto prefetch = [&](int it) {
        int pl = act ? (w * PTS_PER_WARP + it * PTS_PER_IT + g) : 0;
        uint32_t sb = sbase + (it % NSTAGE) * STAGE_B + soff;
        #pragma unroll
        for (int j = 1; j < MNB; j++) {
            int id = s_ids[pl * MNB + j];      // in [0, NPTS]; row NPTS zero
            cpa16(sb + (j - 1) * 512, base + (size_t)id * ROWB + coff);
        }
        cpa_commit();
    };

    float accw = 0.0f;
    prefetch(0);
    prefetch(1);

    #pragma unroll
    for (int it = 0; it < LAP_ITERS; it++) {
        if (it + 2 < LAP_ITERS) prefetch(it + 2);
        else                    cpa_commit();   // empty group keeps wait<2> aligned

        int pl = act ? (w * PTS_PER_WARP + it * PTS_PER_IT + g) : 0;
        int n  = P0 + pl;

        // center = own row (coalesced 640B window per warp); issue before wait
        uint4 cv = *(const uint4*)(base + (size_t)n * ROWB + coff);
        float wnum = s_num[pl];

        cpa_wait<2>();                          // group `it` complete

        uint32_t sb = sbase + (it % NSTAGE) * STAGE_B + soff;

        // neighbors 1..8: two independent half2 chains
        __half2 ha[4], hb[4];
        #pragma unroll
        for (int k = 0; k < 4; k++) { ha[k] = __float2half2_rn(0.0f); hb[k] = ha[k]; }
        #pragma unroll
        for (int j = 1; j < MNB; j++) {
            uint4 v;
            asm volatile("ld.shared.v4.u32 {%0,%1,%2,%3}, [%4];"
                         : "=r"(v.x), "=r"(v.y), "=r"(v.z), "=r"(v.w)
                         : "r"(sb + (j - 1) * 512));
            const __half2* h = (const __half2*)&v;
            if (j & 1) {
                #pragma unroll
                for (int k = 0; k < 4; k++) ha[k] = __hadd2(ha[k], h[k]);
            } else {
                #pragma unroll
                for (int k = 0; k < 4; k++) hb[k] = __hadd2(hb[k], h[k]);
            }
        }

        if (act) {
            const __half2* ch = (const __half2*)&cv;
            #pragma unroll
            for (int k = 0; k < 4; k++) {
                float2 fc = __half22float2(ch[k]);
                float2 fa = __half22float2(ha[k]);
                float2 fb = __half22float2(hb[k]);
                accw += fabsf(fc.x * wnum - fa.x - fb.x)
                      + fabsf(fc.y * wnum - fa.y - fb.y);
            }
        }
    }

    // warp reduce (fixed order), block reduce, one atomic per block
    #pragma unroll
    for (int off = 16; off > 0; off >>= 1)
        accw += __shfl_down_sync(FULL, accw, off);

    if (lane == 0) ws[w] = accw;
    __syncthreads();
    if (tid < LAP_WARPS) {
        float x = ws[tid];
        #pragma unroll
        for (int off = LAP_WARPS / 2; off > 0; off >>= 1)
            x += __shfl_down_sync((1u << LAP_WARPS) - 1u, x, off);
        if (tid == 0)
            atomicAdd(out, x * INV_COUNT);
    }
}

// ---------------------------------------------------------------------------
extern "C" void kernel_launch(void* const* d_in, const int* in_sizes, int n_in,
                              void* d_out, int out_size) {
    const float* gt  = (const float*)d_in[0];   // gt_pc        (B,N,3) f32
    const float* pr  = (const float*)d_in[1];   // predict_pc   (B,N,3) f32
    const int*   nb  = (const int*)  d_in[2];   // neighbor ids (N,9)   i32
    const float* num = (const float*)d_in[3];   // neighbor_num (N,)    f32
    float* out = (float*)d_out;

    int nblk1 = (NPTS + TP - 1) / TP;           // 782
    k_diff<<<nblk1, 256>>>(gt, pr, out);
    k_lap <<<LAP_BLOCKS, LAP_WARPS * 32>>>(nb, num, out);
}

// round 13
// speedup vs baseline: 1.7186x; 1.7186x over previous
#include <cuda_runtime.h>
#include <cuda_fp16.h>
#include <cuda_fp8.h>
#include <cstdint>

#define NPTS   100000
#define BATCH  16
#define MNB    9
#define NSLOTS (NPTS * 3)              /* per-batch floats, divisible by 4 */
#define TP     128                     /* points per k_diff tile           */
#define QB     (TP * 3 / 4)            /* 96 float4 slots per batch        */
#define ROWB   64                      /* padded fp8 row bytes (48B data)  */
#define FP8_SCALE 32.0f
#define INV_COUNT (1.0f / (float)(BATCH * NPTS * 3))
#define SCALE_INV (INV_COUNT / FP8_SCALE)

/* k_lap: 3 lanes/point, 10 pts/warp, 8 warps/block -> 80 pts/block */
#define LAP_WARPS   8
#define PTS_PER_WARP 10
#define PTS_PER_BLK (LAP_WARPS * PTS_PER_WARP)   /* 80   */
#define LAP_BLOCKS  (NPTS / PTS_PER_BLK)         /* 1250, exact */

// Scratch: d = (gt - pr) * 32 in fp8 e4m3. Row n at byte n*64; bytes
// [0,48) hold value (c,b) at byte c*16+b; [48,64) pad (never read).
// Row NPTS is all-zero (reference's zero-padded pc_ext row).
__device__ __align__(128) unsigned char g_dt[(NPTS + 1) * ROWB];

// ---------------------------------------------------------------------------
// Kernel 1: diff + transpose (B,N,3) -> fp8 rows. __ldcs streaming reads so
// the 38MB input stream doesn't evict the scratch from L2.
// ---------------------------------------------------------------------------
__global__ void k_diff(const float* __restrict__ gt, const float* __restrict__ pr,
                       float* __restrict__ out) {
    if (blockIdx.x == 0) {
        if (threadIdx.x == 0) out[0] = 0.0f;
        if (threadIdx.x < 4)   // zero row NPTS (64B)
            ((uint4*)(g_dt + (size_t)NPTS * ROWB))[threadIdx.x] =
                make_uint4(0u, 0u, 0u, 0u);
    }

    __shared__ float4 s4[QB * 16];     // 24KB
    const float* sf = (const float*)s4;

    int n0 = blockIdx.x * TP;
    int slot0 = n0 * 3;

    for (int i = threadIdx.x; i < 16 * QB; i += 256) {
        int b = i / QB;
        int q = i - b * QB;
        int slot = slot0 + q * 4;
        float4 v = make_float4(0.f, 0.f, 0.f, 0.f);
        if (slot < NSLOTS) {
            float4 g = __ldcs((const float4*)(gt + (size_t)b * NSLOTS + slot));
            float4 p = __ldcs((const float4*)(pr + (size_t)b * NSLOTS + slot));
            v = make_float4(g.x - p.x, g.y - p.y, g.z - p.z, g.w - p.w);
        }
        s4[q * 16 + (b ^ (q & 15))] = v;
    }
    __syncthreads();

    // Store: per point 12 data uint32s (48B). Word k of point p covers
    // component c = k>>2, batches b0..b0+3 with b0 = (k&3)*4.
    int valid = NPTS - n0;
    if (valid > TP) valid = TP;
    int total = valid * 12;
    uint32_t* outp = (uint32_t*)g_dt;
    for (int j = threadIdx.x; j < total; j += 256) {
        int p  = j / 12;
        int k  = j - p * 12;
        int c  = k >> 2;
        int b0 = (k & 3) << 2;
        int r  = p * 3 + c;            // slot within tile
        int q  = r >> 2;
        int cmp = r & 3;
        float f0 = sf[4 * (q * 16 + ((b0 + 0) ^ (q & 15))) + cmp] * FP8_SCALE;
        float f1 = sf[4 * (q * 16 + ((b0 + 1) ^ (q & 15))) + cmp] * FP8_SCALE;
        float f2 = sf[4 * (q * 16 + ((b0 + 2) ^ (q & 15))) + cmp] * FP8_SCALE;
        float f3 = sf[4 * (q * 16 + ((b0 + 3) ^ (q & 15))) + cmp] * FP8_SCALE;
        __nv_fp8x2_storage_t lo =
            __nv_cvt_float2_to_fp8x2(make_float2(f0, f1), __NV_SATFINITE, __NV_E4M3);
        __nv_fp8x2_storage_t hi =
            __nv_cvt_float2_to_fp8x2(make_float2(f2, f3), __NV_SATFINITE, __NV_E4M3);
        outp[(size_t)(n0 + p) * 16 + k] = (uint32_t)lo | ((uint32_t)hi << 16);
    }
}

// ---------------------------------------------------------------------------
// fp8x2 -> half2 decode
// ---------------------------------------------------------------------------
__device__ __forceinline__ __half2 fp8x2_h2(uint32_t w16) {
    __half2_raw r = __nv_cvt_fp8x2_to_halfraw2((__nv_fp8x2_storage_t)w16, __NV_E4M3);
    return *(__half2*)&r;
}

// ---------------------------------------------------------------------------
// Kernel 2: gather laplacian. 10 points/warp, 3 lanes/point, lane owns one
// 16B chunk (16 fp8) of the 64B row. Center = own row (coalesced; nb[:,0] is
// arange). 8 random gathers/point, unconditional via the zero row at NPTS.
// 8 independent half2 accumulation chains; final terms in fp32.
// ---------------------------------------------------------------------------
__global__ void k_lap(const int* __restrict__ nb, const float* __restrict__ num,
                      float* __restrict__ out) {
    const unsigned FULL = 0xFFFFFFFFu;
    int tid  = threadIdx.x;
    int lane = tid & 31;
    int w    = tid >> 5;
    int g    = lane / 3;                         // point group 0..9 (10,.. idle)
    int s    = lane - g * 3;                     // chunk 0..2
    bool act = lane < 30;
    int n    = blockIdx.x * PTS_PER_BLK + w * PTS_PER_WARP + (act ? g : 0);

    // neighbor ids 1..8 (L1-cached, 3 lanes/point share)
    int ids[8];
    #pragma unroll
    for (int j = 0; j < 8; j++)
        ids[j] = __ldg(nb + (size_t)n * MNB + 1 + j);   // in [0, NPTS]
    float wnum = __ldg(num + n);

    const char* base = (const char*)g_dt;
    int coff = s * 16;

    // center: own row, coalesced across the warp
    uint4 cv = *(const uint4*)(base + (size_t)n * ROWB + coff);

    // 8 random gathers, unconditional (row NPTS is zero)
    uint4 v[8];
    #pragma unroll
    for (int j = 0; j < 8; j++)
        v[j] = *(const uint4*)(base + (size_t)ids[j] * ROWB + coff);

    // accumulate 16 fp8 values per chunk in 8 independent half2 chains
    __half2 acc[8];
    #pragma unroll
    for (int k = 0; k < 8; k++) acc[k] = __float2half2_rn(0.0f);
    #pragma unroll
    for (int j = 0; j < 8; j++) {
        const uint32_t* wd = (const uint32_t*)&v[j];
        #pragma unroll
        for (int k = 0; k < 4; k++) {
            acc[2 * k]     = __hadd2(acc[2 * k],     fp8x2_h2(wd[k] & 0xFFFFu));
            acc[2 * k + 1] = __hadd2(acc[2 * k + 1], fp8x2_h2(wd[k] >> 16));
        }
    }

    float accw = 0.0f;
    if (act) {
        const uint32_t* cw = (const uint32_t*)&cv;
        #pragma unroll
        for (int k = 0; k < 4; k++) {
            float2 c0 = __half22float2(fp8x2_h2(cw[k] & 0xFFFFu));
            float2 c1 = __half22float2(fp8x2_h2(cw[k] >> 16));
            float2 a0 = __half22float2(acc[2 * k]);
            float2 a1 = __half22float2(acc[2 * k + 1]);
            accw += fabsf(c0.x * wnum - a0.x) + fabsf(c0.y * wnum - a0.y)
                  + fabsf(c1.x * wnum - a1.x) + fabsf(c1.y * wnum - a1.y);
        }
    }

    // warp reduce (fixed order), block reduce, one atomic per block
    #pragma unroll
    for (int off = 16; off > 0; off >>= 1)
        accw += __shfl_down_sync(FULL, accw, off);

    __shared__ float ws[LAP_WARPS];
    if (lane == 0) ws[w] = accw;
    __syncthreads();
    if (tid < LAP_WARPS) {
        float x = ws[tid];
        #pragma unroll
        for (int off = LAP_WARPS / 2; off > 0; off >>= 1)
            x += __shfl_down_sync((1u << LAP_WARPS) - 1u, x, off);
        if (tid == 0)
            atomicAdd(out, x * SCALE_INV);
    }
}

// ---------------------------------------------------------------------------
extern "C" void kernel_launch(void* const* d_in, const int* in_sizes, int n_in,
                              void* d_out, int out_size) {
    const float* gt  = (const float*)d_in[0];   // gt_pc        (B,N,3) f32
    const float* pr  = (const float*)d_in[1];   // predict_pc   (B,N,3) f32
    const int*   nb  = (const int*)  d_in[2];   // neighbor ids (N,9)   i32
    const float* num = (const float*)d_in[3];   // neighbor_num (N,)    f32
    float* out = (float*)d_out;

    int nblk1 = (NPTS + TP - 1) / TP;           // 782
    k_diff<<<nblk1, 256>>>(gt, pr, out);
    k_lap <<<LAP_BLOCKS, LAP_WARPS * 32>>>(nb, num, out);
}

// round 14
// speedup vs baseline: 1.8082x; 1.0521x over previous
#include <cuda_runtime.h>
#include <cuda_fp16.h>
#include <cuda_fp8.h>
#include <cstdint>

#define NPTS   100000
#define BATCH  16
#define MNB    9
#define NSLOTS (NPTS * 3)              /* per-batch floats, divisible by 4 */
#define TP     128                     /* points per k_diff tile           */
#define QB     (TP * 3 / 4)            /* 96 float4 slots per batch        */
#define ROWB   64                      /* padded fp8 row bytes (48B data)  */
#define FP8_SCALE 32.0f
#define INV_COUNT (1.0f / (float)(BATCH * NPTS * 3))
#define SCALE_INV (INV_COUNT / FP8_SCALE)

/* k_lap: 3 lanes/point, 10 pts/warp, 16 warps/block -> 160 pts/block */
#define LAP_WARPS   16
#define PTS_PER_WARP 10
#define PTS_PER_BLK (LAP_WARPS * PTS_PER_WARP)   /* 160  */
#define LAP_BLOCKS  (NPTS / PTS_PER_BLK)         /* 625, exact */

// Scratch: d = (gt - pr) * 32 in fp8 e4m3. Row n at byte n*64; bytes
// [0,48) hold value (c,b) at byte c*16+b; [48,64) pad (never read).
// Row NPTS is all-zero (reference's zero-padded pc_ext row).
__device__ __align__(128) unsigned char g_dt[(NPTS + 1) * ROWB];

// ---------------------------------------------------------------------------
// Kernel 1: diff + transpose (B,N,3) -> fp8 rows. Default-cached reads (the
// whole footprint is L2-resident across graph replays). Wide STG.128 stores.
// ---------------------------------------------------------------------------
__global__ void k_diff(const float* __restrict__ gt, const float* __restrict__ pr,
                       float* __restrict__ out) {
    if (blockIdx.x == 0) {
        if (threadIdx.x == 0) out[0] = 0.0f;
        if (threadIdx.x < 4)   // zero row NPTS (64B)
            ((uint4*)(g_dt + (size_t)NPTS * ROWB))[threadIdx.x] =
                make_uint4(0u, 0u, 0u, 0u);
    }

    __shared__ float4 s4[QB * 16];     // 24KB
    const float* sf = (const float*)s4;

    int n0 = blockIdx.x * TP;
    int slot0 = n0 * 3;

    // Load phase: i = b*QB + q; coalesced float4 reads per batch stream;
    // smem bank = 4*((b&7)^(q&7)) -> conflict-free.
    for (int i = threadIdx.x; i < 16 * QB; i += 256) {
        int b = i / QB;
        int q = i - b * QB;
        int slot = slot0 + q * 4;
        float4 v = make_float4(0.f, 0.f, 0.f, 0.f);
        if (slot < NSLOTS) {
            float4 g = *(const float4*)(gt + (size_t)b * NSLOTS + slot);
            float4 p = *(const float4*)(pr + (size_t)b * NSLOTS + slot);
            v = make_float4(g.x - p.x, g.y - p.y, g.z - p.z, g.w - p.w);
        }
        s4[q * 16 + (b ^ (q & 15))] = v;
    }
    __syncthreads();

    // Store phase: one uint4 per (point, component) = 16 fp8 batch values.
    // j in [0, valid*3): p = j/3, c = j%3. Output at n*64 + c*16 (16B-aligned).
    int valid = NPTS - n0;
    if (valid > TP) valid = TP;
    int total = valid * 3;
    for (int j = threadIdx.x; j < total; j += 256) {
        int p = j / 3;
        int c = j - 3 * p;
        int r = p * 3 + c;             // slot within tile
        int q = r >> 2;
        int cmp = r & 3;
        uint32_t wds[4];
        #pragma unroll
        for (int bq = 0; bq < 4; bq++) {
            int b0 = bq << 2;
            float f0 = sf[4 * (q * 16 + ((b0 + 0) ^ (q & 15))) + cmp] * FP8_SCALE;
            float f1 = sf[4 * (q * 16 + ((b0 + 1) ^ (q & 15))) + cmp] * FP8_SCALE;
            float f2 = sf[4 * (q * 16 + ((b0 + 2) ^ (q & 15))) + cmp] * FP8_SCALE;
            float f3 = sf[4 * (q * 16 + ((b0 + 3) ^ (q & 15))) + cmp] * FP8_SCALE;
            __nv_fp8x2_storage_t lo =
                __nv_cvt_float2_to_fp8x2(make_float2(f0, f1), __NV_SATFINITE, __NV_E4M3);
            __nv_fp8x2_storage_t hi =
                __nv_cvt_float2_to_fp8x2(make_float2(f2, f3), __NV_SATFINITE, __NV_E4M3);
            wds[bq] = (uint32_t)lo | ((uint32_t)hi << 16);
        }
        *(uint4*)(g_dt + (size_t)(n0 + p) * ROWB + c * 16) =
            make_uint4(wds[0], wds[1], wds[2], wds[3]);
    }
}

// ---------------------------------------------------------------------------
// fp8x2 -> half2 decode
// ---------------------------------------------------------------------------
__device__ __forceinline__ __half2 fp8x2_h2(uint32_t w16) {
    __half2_raw r = __nv_cvt_fp8x2_to_halfraw2((__nv_fp8x2_storage_t)w16, __NV_E4M3);
    return *(__half2*)&r;
}

// ---------------------------------------------------------------------------
// Kernel 2: gather laplacian. 10 points/warp, 3 lanes/point, lane owns one
// 16B chunk (16 fp8) of the 64B row. Center = own row (coalesced; nb[:,0] is
// arange). 8 random gathers/point, unconditional via the zero row at NPTS.
// 8 independent half2 accumulation chains; final terms in fp32.
// ---------------------------------------------------------------------------
__global__ void __launch_bounds__(LAP_WARPS * 32)
k_lap(const int* __restrict__ nb, const float* __restrict__ num,
      float* __restrict__ out) {
    const unsigned FULL = 0xFFFFFFFFu;
    int tid  = threadIdx.x;
    int lane = tid & 31;
    int w    = tid >> 5;
    int g    = lane / 3;                         // point group 0..9 (10 -> idle)
    int s    = lane - g * 3;                     // chunk 0..2
    bool act = lane < 30;
    int n    = blockIdx.x * PTS_PER_BLK + w * PTS_PER_WARP + (act ? g : 0);

    // neighbor ids 1..8 (L1-cached, 3 lanes/point share)
    int ids[8];
    #pragma unroll
    for (int j = 0; j < 8; j++)
        ids[j] = __ldg(nb + (size_t)n * MNB + 1 + j);   // in [0, NPTS]
    float wnum = __ldg(num + n);

    const char* base = (const char*)g_dt;
    int coff = s * 16;

    // center: own row, coalesced across the warp
    uint4 cv = *(const uint4*)(base + (size_t)n * ROWB + coff);

    // 8 random gathers, unconditional (row NPTS is zero)
    uint4 v[8];
    #pragma unroll
    for (int j = 0; j < 8; j++)
        v[j] = *(const uint4*)(base + (size_t)ids[j] * ROWB + coff);

    // accumulate 16 fp8 values per chunk in 8 independent half2 chains
    __half2 acc[8];
    #pragma unroll
    for (int k = 0; k < 8; k++) acc[k] = __float2half2_rn(0.0f);
    #pragma unroll
    for (int j = 0; j < 8; j++) {
        const uint32_t* wd = (const uint32_t*)&v[j];
        #pragma unroll
        for (int k = 0; k < 4; k++) {
            acc[2 * k]     = __hadd2(acc[2 * k],     fp8x2_h2(wd[k] & 0xFFFFu));
            acc[2 * k + 1] = __hadd2(acc[2 * k + 1], fp8x2_h2(wd[k] >> 16));
        }
    }

    float accw = 0.0f;
    if (act) {
        const uint32_t* cw = (const uint32_t*)&cv;
        #pragma unroll
        for (int k = 0; k < 4; k++) {
            float2 c0 = __half22float2(fp8x2_h2(cw[k] & 0xFFFFu));
            float2 c1 = __half22float2(fp8x2_h2(cw[k] >> 16));
            float2 a0 = __half22float2(acc[2 * k]);
            float2 a1 = __half22float2(acc[2 * k + 1]);
            accw += fabsf(c0.x * wnum - a0.x) + fabsf(c0.y * wnum - a0.y)
                  + fabsf(c1.x * wnum - a1.x) + fabsf(c1.y * wnum - a1.y);
        }
    }

    // warp reduce (fixed order), block reduce, one atomic per block
    #pragma unroll
    for (int off = 16; off > 0; off >>= 1)
        accw += __shfl_down_sync(FULL, accw, off);

    __shared__ float ws[LAP_WARPS];
    if (lane == 0) ws[w] = accw;
    __syncthreads();
    if (tid < LAP_WARPS) {
        float x = ws[tid];
        #pragma unroll
        for (int off = LAP_WARPS / 2; off > 0; off >>= 1)
            x += __shfl_down_sync(0xFFFFu, x, off);
        if (tid == 0)
            atomicAdd(out, x * SCALE_INV);
    }
}

// ---------------------------------------------------------------------------
extern "C" void kernel_launch(void* const* d_in, const int* in_sizes, int n_in,
                              void* d_out, int out_size) {
    const float* gt  = (const float*)d_in[0];   // gt_pc        (B,N,3) f32
    const float* pr  = (const float*)d_in[1];   // predict_pc   (B,N,3) f32
    const int*   nb  = (const int*)  d_in[2];   // neighbor ids (N,9)   i32
    const float* num = (const float*)d_in[3];   // neighbor_num (N,)    f32
    float* out = (float*)d_out;

    int nblk1 = (NPTS + TP - 1) / TP;           // 782
    k_diff<<<nblk1, 256>>>(gt, pr, out);
    k_lap <<<LAP_BLOCKS, LAP_WARPS * 32>>>(nb, num, out);
}

// round 15
// speedup vs baseline: 1.8425x; 1.0190x over previous
#include <cuda_runtime.h>
#include <cuda_fp16.h>
#include <cuda_fp8.h>
#include <cstdint>

#define NPTS   100000
#define BATCH  16
#define MNB    9
#define NSLOTS (NPTS * 3)              /* per-batch floats, divisible by 4 */
#define TP     128                     /* points per k_diff tile           */
#define QB     (TP * 3 / 4)            /* 96 float4 slots per batch        */
#define ROWB   64                      /* padded fp8 row bytes (48B data)  */
#define FP8_SCALE 32.0f
#define INV_COUNT (1.0f / (float)(BATCH * NPTS * 3))
#define SCALE_INV (INV_COUNT / FP8_SCALE)

/* k_lap: 3 lanes/point, 10 pts/warp, 16 warps/block -> 160 pts/block */
#define LAP_WARPS   16
#define PTS_PER_WARP 10
#define PTS_PER_BLK (LAP_WARPS * PTS_PER_WARP)   /* 160  */
#define LAP_BLOCKS  (NPTS / PTS_PER_BLK)         /* 625, exact */

// Scratch: d = (gt - pr) * 32 in fp8 e4m3. Row n at byte n*64; bytes
// [0,48) hold value (c,b) at byte c*16+b; [48,64) pad (never read).
// Row NPTS is all-zero (reference's zero-padded pc_ext row).
__device__ __align__(128) unsigned char g_dt[(NPTS + 1) * ROWB];

// ---------------------------------------------------------------------------
// Kernel 1: diff + transpose (B,N,3) -> fp8 rows. Wide STG.128 stores.
// Signals PDL dependents after its stores so k_lap can ramp up early.
// ---------------------------------------------------------------------------
__global__ void k_diff(const float* __restrict__ gt, const float* __restrict__ pr,
                       float* __restrict__ out) {
    if (blockIdx.x == 0) {
        if (threadIdx.x == 0) out[0] = 0.0f;
        if (threadIdx.x < 4)   // zero row NPTS (64B)
            ((uint4*)(g_dt + (size_t)NPTS * ROWB))[threadIdx.x] =
                make_uint4(0u, 0u, 0u, 0u);
    }

    __shared__ float4 s4[QB * 16];     // 24KB
    const float* sf = (const float*)s4;

    int n0 = blockIdx.x * TP;
    int slot0 = n0 * 3;

    // Load phase: i = b*QB + q; coalesced float4 reads per batch stream;
    // smem bank = 4*((b&7)^(q&7)) -> conflict-free.
    for (int i = threadIdx.x; i < 16 * QB; i += 256) {
        int b = i / QB;
        int q = i - b * QB;
        int slot = slot0 + q * 4;
        float4 v = make_float4(0.f, 0.f, 0.f, 0.f);
        if (slot < NSLOTS) {
            float4 g = *(const float4*)(gt + (size_t)b * NSLOTS + slot);
            float4 p = *(const float4*)(pr + (size_t)b * NSLOTS + slot);
            v = make_float4(g.x - p.x, g.y - p.y, g.z - p.z, g.w - p.w);
        }
        s4[q * 16 + (b ^ (q & 15))] = v;
    }
    __syncthreads();

    // Store phase: one uint4 per (point, component) = 16 fp8 batch values.
    int valid = NPTS - n0;
    if (valid > TP) valid = TP;
    int total = valid * 3;
    for (int j = threadIdx.x; j < total; j += 256) {
        int p = j / 3;
        int c = j - 3 * p;
        int r = p * 3 + c;             // slot within tile
        int q = r >> 2;
        int cmp = r & 3;
        uint32_t wds[4];
        #pragma unroll
        for (int bq = 0; bq < 4; bq++) {
            int b0 = bq << 2;
            float f0 = sf[4 * (q * 16 + ((b0 + 0) ^ (q & 15))) + cmp] * FP8_SCALE;
            float f1 = sf[4 * (q * 16 + ((b0 + 1) ^ (q & 15))) + cmp] * FP8_SCALE;
            float f2 = sf[4 * (q * 16 + ((b0 + 2) ^ (q & 15))) + cmp] * FP8_SCALE;
            float f3 = sf[4 * (q * 16 + ((b0 + 3) ^ (q & 15))) + cmp] * FP8_SCALE;
            __nv_fp8x2_storage_t lo =
                __nv_cvt_float2_to_fp8x2(make_float2(f0, f1), __NV_SATFINITE, __NV_E4M3);
            __nv_fp8x2_storage_t hi =
                __nv_cvt_float2_to_fp8x2(make_float2(f2, f3), __NV_SATFINITE, __NV_E4M3);
            wds[bq] = (uint32_t)lo | ((uint32_t)hi << 16);
        }
        *(uint4*)(g_dt + (size_t)(n0 + p) * ROWB + c * 16) =
            make_uint4(wds[0], wds[1], wds[2], wds[3]);
    }

    // PDL: all this block's scratch stores are issued; allow dependents.
    asm volatile("griddepcontrol.launch_dependents;" ::: "memory");
}

// ---------------------------------------------------------------------------
// fp8x2 -> half2 decode
// ---------------------------------------------------------------------------
__device__ __forceinline__ __half2 fp8x2_h2(uint32_t w16) {
    __half2_raw r = __nv_cvt_fp8x2_to_halfraw2((__nv_fp8x2_storage_t)w16, __NV_E4M3);
    return *(__half2*)&r;
}

// ---------------------------------------------------------------------------
// Kernel 2: gather laplacian. 10 points/warp, 3 lanes/point, lane owns one
// 16B chunk (16 fp8) of the 64B row. Launched with PDL: loads ids/num
// (independent of k_diff) before griddepcontrol.wait, then gathers.
// ---------------------------------------------------------------------------
__global__ void __launch_bounds__(LAP_WARPS * 32)
k_lap(const int* __restrict__ nb, const float* __restrict__ num,
      float* __restrict__ out) {
    const unsigned FULL = 0xFFFFFFFFu;
    int tid  = threadIdx.x;
    int lane = tid & 31;
    int w    = tid >> 5;
    int g    = lane / 3;                         // point group 0..9 (10 -> idle)
    int s    = lane - g * 3;                     // chunk 0..2
    bool act = lane < 30;
    int n    = blockIdx.x * PTS_PER_BLK + w * PTS_PER_WARP + (act ? g : 0);

    // neighbor ids 1..8 + num: pure input reads, safe before the PDL wait
    int ids[8];
    #pragma unroll
    for (int j = 0; j < 8; j++)
        ids[j] = __ldg(nb + (size_t)n * MNB + 1 + j);   // in [0, NPTS]
    float wnum = __ldg(num + n);

    // PDL: block until k_diff's stores are visible
    asm volatile("griddepcontrol.wait;" ::: "memory");

    const char* base = (const char*)g_dt;
    int coff = s * 16;

    // center: own row (nb[:,0] is arange), coalesced across the warp
    uint4 cv = *(const uint4*)(base + (size_t)n * ROWB + coff);

    // 8 random gathers, unconditional (row NPTS is zero)
    uint4 v[8];
    #pragma unroll
    for (int j = 0; j < 8; j++)
        v[j] = *(const uint4*)(base + (size_t)ids[j] * ROWB + coff);

    // accumulate 16 fp8 values per chunk in 8 independent half2 chains
    __half2 acc[8];
    #pragma unroll
    for (int k = 0; k < 8; k++) acc[k] = __float2half2_rn(0.0f);
    #pragma unroll
    for (int j = 0; j < 8; j++) {
        const uint32_t* wd = (const uint32_t*)&v[j];
        #pragma unroll
        for (int k = 0; k < 4; k++) {
            acc[2 * k]     = __hadd2(acc[2 * k],     fp8x2_h2(wd[k] & 0xFFFFu));
            acc[2 * k + 1] = __hadd2(acc[2 * k + 1], fp8x2_h2(wd[k] >> 16));
        }
    }

    float accw = 0.0f;
    if (act) {
        const uint32_t* cw = (const uint32_t*)&cv;
        #pragma unroll
        for (int k = 0; k < 4; k++) {
            float2 c0 = __half22float2(fp8x2_h2(cw[k] & 0xFFFFu));
            float2 c1 = __half22float2(fp8x2_h2(cw[k] >> 16));
            float2 a0 = __half22float2(acc[2 * k]);
            float2 a1 = __half22float2(acc[2 * k + 1]);
            accw += fabsf(c0.x * wnum - a0.x) + fabsf(c0.y * wnum - a0.y)
                  + fabsf(c1.x * wnum - a1.x) + fabsf(c1.y * wnum - a1.y);
        }
    }

    // warp reduce (fixed order), block reduce, one atomic per block
    #pragma unroll
    for (int off = 16; off > 0; off >>= 1)
        accw += __shfl_down_sync(FULL, accw, off);

    __shared__ float ws[LAP_WARPS];
    if (lane == 0) ws[w] = accw;
    __syncthreads();
    if (tid < LAP_WARPS) {
        float x = ws[tid];
        #pragma unroll
        for (int off = LAP_WARPS / 2; off > 0; off >>= 1)
            x += __shfl_down_sync(0xFFFFu, x, off);
        if (tid == 0)
            atomicAdd(out, x * SCALE_INV);
    }
}

// ---------------------------------------------------------------------------
extern "C" void kernel_launch(void* const* d_in, const int* in_sizes, int n_in,
                              void* d_out, int out_size) {
    const float* gt  = (const float*)d_in[0];   // gt_pc        (B,N,3) f32
    const float* pr  = (const float*)d_in[1];   // predict_pc   (B,N,3) f32
    const int*   nb  = (const int*)  d_in[2];   // neighbor ids (N,9)   i32
    const float* num = (const float*)d_in[3];   // neighbor_num (N,)    f32
    float* out = (float*)d_out;

    int nblk1 = (NPTS + TP - 1) / TP;           // 782
    k_diff<<<nblk1, 256>>>(gt, pr, out);

    // k_lap with programmatic dependent launch: overlaps its prologue with
    // k_diff's tail; griddepcontrol.wait guards the g_dt reads.
    cudaLaunchConfig_t cfg = {};
    cfg.gridDim  = dim3(LAP_BLOCKS);
    cfg.blockDim = dim3(LAP_WARPS * 32);
    cfg.dynamicSmemBytes = 0;
    cfg.stream = 0;                              // legacy default (capture) stream
    cudaLaunchAttribute attr[1];
    attr[0].id = cudaLaunchAttributeProgrammaticStreamSerialization;
    attr[0].val.programmaticStreamSerializationAllowed = 1;
    cfg.attrs = attr;
    cfg.numAttrs = 1;
    cudaLaunchKernelEx(&cfg, k_lap, nb, num, out);
}

// round 16
// speedup vs baseline: 1.8854x; 1.0233x over previous
#include <cuda_runtime.h>
#include <cuda_fp16.h>
#include <cuda_fp8.h>
#include <cstdint>

#define NPTS   100000
#define BATCH  16
#define MNB    9
#define NSLOTS (NPTS * 3)              /* per-batch floats, divisible by 4 */
#define TP     128                     /* points per k_diff tile           */
#define QB     (TP * 3 / 4)            /* 96 float4 slots per batch        */
#define ROWB   64                      /* padded fp8 row bytes (48B data)  */
#define FP8_SCALE 32.0f
#define INV_COUNT (1.0f / (float)(BATCH * NPTS * 3))
#define SCALE_INV (INV_COUNT / FP8_SCALE)

/* k_lap: 3 lanes/point, 10 pts/warp, 16 warps/block -> 160 pts/block */
#define LAP_WARPS   16
#define PTS_PER_WARP 10
#define PTS_PER_BLK (LAP_WARPS * PTS_PER_WARP)   /* 160  */
#define LAP_BLOCKS  (NPTS / PTS_PER_BLK)         /* 625, exact */

// Scratch: d = (gt - pr) * 32 in fp8 e4m3. Row n at byte n*64; bytes
// [0,48) hold value (c,b) at byte c*16+b; [48,64) pad (never read).
// Row NPTS is all-zero (reference's zero-padded pc_ext row).
__device__ __align__(128) unsigned char g_dt[(NPTS + 1) * ROWB];

// ---------------------------------------------------------------------------
// Kernel 1: diff + transpose (B,N,3) -> fp8 rows. Wide STG.128 stores.
// Signals PDL dependents after its stores so k_lap can ramp up early.
// ---------------------------------------------------------------------------
__global__ void k_diff(const float* __restrict__ gt, const float* __restrict__ pr,
                       float* __restrict__ out) {
    if (blockIdx.x == 0) {
        if (threadIdx.x == 0) out[0] = 0.0f;
        if (threadIdx.x < 4)   // zero row NPTS (64B)
            ((uint4*)(g_dt + (size_t)NPTS * ROWB))[threadIdx.x] =
                make_uint4(0u, 0u, 0u, 0u);
    }

    __shared__ float4 s4[QB * 16];     // 24KB
    const float* sf = (const float*)s4;

    int n0 = blockIdx.x * TP;
    int slot0 = n0 * 3;

    // Load phase: i = b*QB + q; coalesced float4 reads per batch stream;
    // smem bank = 4*((b&7)^(q&7)) -> conflict-free.
    for (int i = threadIdx.x; i < 16 * QB; i += 256) {
        int b = i / QB;
        int q = i - b * QB;
        int slot = slot0 + q * 4;
        float4 v = make_float4(0.f, 0.f, 0.f, 0.f);
        if (slot < NSLOTS) {
            float4 g = *(const float4*)(gt + (size_t)b * NSLOTS + slot);
            float4 p = *(const float4*)(pr + (size_t)b * NSLOTS + slot);
            v = make_float4(g.x - p.x, g.y - p.y, g.z - p.z, g.w - p.w);
        }
        s4[q * 16 + (b ^ (q & 15))] = v;
    }
    __syncthreads();

    // Store phase: one uint4 per (point, component) = 16 fp8 batch values.
    int valid = NPTS - n0;
    if (valid > TP) valid = TP;
    int total = valid * 3;
    for (int j = threadIdx.x; j < total; j += 256) {
        int p = j / 3;
        int c = j - 3 * p;
        int r = p * 3 + c;             // slot within tile
        int q = r >> 2;
        int cmp = r & 3;
        uint32_t wds[4];
        #pragma unroll
        for (int bq = 0; bq < 4; bq++) {
            int b0 = bq << 2;
            float f0 = sf[4 * (q * 16 + ((b0 + 0) ^ (q & 15))) + cmp] * FP8_SCALE;
            float f1 = sf[4 * (q * 16 + ((b0 + 1) ^ (q & 15))) + cmp] * FP8_SCALE;
            float f2 = sf[4 * (q * 16 + ((b0 + 2) ^ (q & 15))) + cmp] * FP8_SCALE;
            float f3 = sf[4 * (q * 16 + ((b0 + 3) ^ (q & 15))) + cmp] * FP8_SCALE;
            __nv_fp8x2_storage_t lo =
                __nv_cvt_float2_to_fp8x2(make_float2(f0, f1), __NV_SATFINITE, __NV_E4M3);
            __nv_fp8x2_storage_t hi =
                __nv_cvt_float2_to_fp8x2(make_float2(f2, f3), __NV_SATFINITE, __NV_E4M3);
            wds[bq] = (uint32_t)lo | ((uint32_t)hi << 16);
        }
        *(uint4*)(g_dt + (size_t)(n0 + p) * ROWB + c * 16) =
            make_uint4(wds[0], wds[1], wds[2], wds[3]);
    }

    // PDL: all this block's scratch stores are issued; allow dependents.
    asm volatile("griddepcontrol.launch_dependents;" ::: "memory");
}

// ---------------------------------------------------------------------------
// fp8x2 -> half2 decode
// ---------------------------------------------------------------------------
__device__ __forceinline__ __half2 fp8x2_h2(uint32_t w16) {
    __half2_raw r = __nv_cvt_fp8x2_to_halfraw2((__nv_fp8x2_storage_t)w16, __NV_E4M3);
    return *(__half2*)&r;
}

// ---------------------------------------------------------------------------
// Kernel 2: gather laplacian. 10 points/warp, 3 lanes/point, lane owns one
// 16B chunk (16 fp8) of the 64B row. The 8 random gathers are issued in ONE
// asm block (32 live result registers) -> ptxas cannot serialize them: true
// MLP=8 per lane. fp16 epilogue. PDL-launched.
// ---------------------------------------------------------------------------
__global__ void __launch_bounds__(LAP_WARPS * 32)
k_lap(const int* __restrict__ nb, const float* __restrict__ num,
      float* __restrict__ out) {
    const unsigned FULL = 0xFFFFFFFFu;
    int tid  = threadIdx.x;
    int lane = tid & 31;
    int w    = tid >> 5;
    int g    = lane / 3;                         // point group 0..9 (10 -> idle)
    int s    = lane - g * 3;                     // chunk 0..2
    bool act = lane < 30;
    int n    = blockIdx.x * PTS_PER_BLK + w * PTS_PER_WARP + (act ? g : 0);

    // neighbor ids 1..8 + num: pure input reads, safe before the PDL wait
    int ids[8];
    #pragma unroll
    for (int j = 0; j < 8; j++)
        ids[j] = __ldg(nb + (size_t)n * MNB + 1 + j);   // in [0, NPTS]
    float wnum = __ldg(num + n);

    // PDL: block until k_diff's stores are visible
    asm volatile("griddepcontrol.wait;" ::: "memory");

    const char* base = (const char*)g_dt;
    int coff = s * 16;

    // center: own row (nb[:,0] is arange), coalesced across the warp
    uint4 cv = *(const uint4*)(base + (size_t)n * ROWB + coff);

    // 8 random gathers in ONE asm block: forced MLP=8, 32 live registers.
    const char* p0 = base + (size_t)ids[0] * ROWB + coff;
    const char* p1 = base + (size_t)ids[1] * ROWB + coff;
    const char* p2 = base + (size_t)ids[2] * ROWB + coff;
    const char* p3 = base + (size_t)ids[3] * ROWB + coff;
    const char* p4 = base + (size_t)ids[4] * ROWB + coff;
    const char* p5 = base + (size_t)ids[5] * ROWB + coff;
    const char* p6 = base + (size_t)ids[6] * ROWB + coff;
    const char* p7 = base + (size_t)ids[7] * ROWB + coff;
    uint32_t r[32];
    asm volatile(
        "ld.global.nc.v4.u32 {%0,%1,%2,%3},     [%32];\n\t"
        "ld.global.nc.v4.u32 {%4,%5,%6,%7},     [%33];\n\t"
        "ld.global.nc.v4.u32 {%8,%9,%10,%11},   [%34];\n\t"
        "ld.global.nc.v4.u32 {%12,%13,%14,%15}, [%35];\n\t"
        "ld.global.nc.v4.u32 {%16,%17,%18,%19}, [%36];\n\t"
        "ld.global.nc.v4.u32 {%20,%21,%22,%23}, [%37];\n\t"
        "ld.global.nc.v4.u32 {%24,%25,%26,%27}, [%38];\n\t"
        "ld.global.nc.v4.u32 {%28,%29,%30,%31}, [%39];\n\t"
        : "=r"(r[0]),  "=r"(r[1]),  "=r"(r[2]),  "=r"(r[3]),
          "=r"(r[4]),  "=r"(r[5]),  "=r"(r[6]),  "=r"(r[7]),
          "=r"(r[8]),  "=r"(r[9]),  "=r"(r[10]), "=r"(r[11]),
          "=r"(r[12]), "=r"(r[13]), "=r"(r[14]), "=r"(r[15]),
          "=r"(r[16]), "=r"(r[17]), "=r"(r[18]), "=r"(r[19]),
          "=r"(r[20]), "=r"(r[21]), "=r"(r[22]), "=r"(r[23]),
          "=r"(r[24]), "=r"(r[25]), "=r"(r[26]), "=r"(r[27]),
          "=r"(r[28]), "=r"(r[29]), "=r"(r[30]), "=r"(r[31])
        : "l"(p0), "l"(p1), "l"(p2), "l"(p3),
          "l"(p4), "l"(p5), "l"(p6), "l"(p7));

    // accumulate 16 fp8 positions in 8 independent half2 chains
    __half2 acc[8];
    #pragma unroll
    for (int k = 0; k < 8; k++) acc[k] = __float2half2_rn(0.0f);
    #pragma unroll
    for (int j = 0; j < 8; j++) {
        #pragma unroll
        for (int k = 0; k < 4; k++) {
            uint32_t wd = r[4 * j + k];
            acc[2 * k]     = __hadd2(acc[2 * k],     fp8x2_h2(wd & 0xFFFFu));
            acc[2 * k + 1] = __hadd2(acc[2 * k + 1], fp8x2_h2(wd >> 16));
        }
    }

    // fp16 epilogue: |center*num - sum| accumulated in half2, one final cvt
    float accw = 0.0f;
    if (act) {
        __half2 wn2 = __float2half2_rn(wnum);
        const uint32_t* cw = (const uint32_t*)&cv;
        __half2 t = __float2half2_rn(0.0f);
        #pragma unroll
        for (int k = 0; k < 4; k++) {
            __half2 clo = fp8x2_h2(cw[k] & 0xFFFFu);
            __half2 chi = fp8x2_h2(cw[k] >> 16);
            t = __hadd2(t, __habs2(__hsub2(__hmul2(clo, wn2), acc[2 * k])));
            t = __hadd2(t, __habs2(__hsub2(__hmul2(chi, wn2), acc[2 * k + 1])));
        }
        float2 tf = __half22float2(t);
        accw = tf.x + tf.y;
    }

    // warp reduce (fixed order), block reduce, one atomic per block
    #pragma unroll
    for (int off = 16; off > 0; off >>= 1)
        accw += __shfl_down_sync(FULL, accw, off);

    __shared__ float ws[LAP_WARPS];
    if (lane == 0) ws[w] = accw;
    __syncthreads();
    if (tid < LAP_WARPS) {
        float x = ws[tid];
        #pragma unroll
        for (int off = LAP_WARPS / 2; off > 0; off >>= 1)
            x += __shfl_down_sync(0xFFFFu, x, off);
        if (tid == 0)
            atomicAdd(out, x * SCALE_INV);
    }
}

// ---------------------------------------------------------------------------
extern "C" void kernel_launch(void* const* d_in, const int* in_sizes, int n_in,
                              void* d_out, int out_size) {
    const float* gt  = (const float*)d_in[0];   // gt_pc        (B,N,3) f32
    const float* pr  = (const float*)d_in[1];   // predict_pc   (B,N,3) f32
    const int*   nb  = (const int*)  d_in[2];   // neighbor ids (N,9)   i32
    const float* num = (const float*)d_in[3];   // neighbor_num (N,)    f32
    float* out = (float*)d_out;

    int nblk1 = (NPTS + TP - 1) / TP;           // 782
    k_diff<<<nblk1, 256>>>(gt, pr, out);

    // k_lap with programmatic dependent launch: overlaps its prologue with
    // k_diff's tail; griddepcontrol.wait guards the g_dt reads.
    cudaLaunchConfig_t cfg = {};
    cfg.gridDim  = dim3(LAP_BLOCKS);
    cfg.blockDim = dim3(LAP_WARPS * 32);
    cfg.dynamicSmemBytes = 0;
    cfg.stream = 0;                              // legacy default (capture) stream
    cudaLaunchAttribute attr[1];
    attr[0].id = cudaLaunchAttributeProgrammaticStreamSerialization;
    attr[0].val.programmaticStreamSerializationAllowed = 1;
    cfg.attrs = attr;
    cfg.numAttrs = 1;
    cudaLaunchKernelEx(&cfg, k_lap, nb, num, out);
}